// round 2
// baseline (speedup 1.0000x reference)
#include <cuda_runtime.h>
#include <math.h>

#define B_  4
#define S_  2048
#define D_  512
#define H_  8
#define HD_ 64
#define NR  (B_ * S_)   // 8192 rows

// Scratch: __device__ globals (no allocation allowed in kernel_launch).
__device__ __align__(16) float g_fused[NR * D_];
__device__ __align__(16) float g_Q[NR * D_];
__device__ __align__(16) float g_K[NR * D_];
__device__ __align__(16) float g_V[NR * D_];
__device__ __align__(16) float g_att[NR * D_];

// ---------------------------------------------------------------------------
// Tiled fp32 SGEMM with bias: C[M,N] = A[M,K] @ Bw[K,N] + bias.
// Concat support: logical A row r is A[r][0..KA) ++ A2[r][0..K-KA). For a
// plain GEMM pass A2 = A and KA = K. K-tile (16) never straddles KA (512|16).
// 128x128 block tile, 8x8 per thread, 256 threads.
// ---------------------------------------------------------------------------
__global__ __launch_bounds__(256) void sgemm_bias(
    const float* __restrict__ A, const float* __restrict__ A2, int KA,
    const float* __restrict__ Bw, const float* __restrict__ bias,
    float* __restrict__ C, int M, int N, int K)
{
    __shared__ __align__(16) float As[16][128];
    __shared__ __align__(16) float Bs[16][128];

    const int tid  = threadIdx.x;
    const int tx   = tid & 15;       // 0..15 -> output cols
    const int ty   = tid >> 4;       // 0..15 -> output rows
    const int row0 = blockIdx.y * 128;
    const int col0 = blockIdx.x * 128;

    const int arow = tid >> 2;        // 0..63
    const int akk  = (tid & 3) * 4;   // 0,4,8,12
    const int bkk  = tid >> 5;        // 0..7
    const int bc   = (tid & 31) * 4;  // 0..124

    float acc[8][8];
    #pragma unroll
    for (int i = 0; i < 8; i++)
        #pragma unroll
        for (int j = 0; j < 8; j++) acc[i][j] = 0.0f;

    for (int k0 = 0; k0 < K; k0 += 16) {
        const float* src = (k0 < KA) ? A : A2;
        const int koff = (k0 < KA) ? k0 : (k0 - KA);

        // A tile -> As[kk][r] (transposed)
        #pragma unroll
        for (int half = 0; half < 2; half++) {
            int r = arow + half * 64;
            float4 v = *(const float4*)&src[(size_t)(row0 + r) * KA + koff + akk];
            As[akk + 0][r] = v.x; As[akk + 1][r] = v.y;
            As[akk + 2][r] = v.z; As[akk + 3][r] = v.w;
        }
        // B tile -> Bs[kk][c]
        #pragma unroll
        for (int half = 0; half < 2; half++) {
            int kk = bkk + half * 8;
            *(float4*)&Bs[kk][bc] =
                *(const float4*)&Bw[(size_t)(k0 + kk) * N + col0 + bc];
        }
        __syncthreads();

        #pragma unroll
        for (int kk = 0; kk < 16; kk++) {
            float4 a0 = *(const float4*)&As[kk][ty * 4];
            float4 a1 = *(const float4*)&As[kk][ty * 4 + 64];
            float4 b0 = *(const float4*)&Bs[kk][tx * 4];
            float4 b1 = *(const float4*)&Bs[kk][tx * 4 + 64];
            float a[8] = {a0.x, a0.y, a0.z, a0.w, a1.x, a1.y, a1.z, a1.w};
            float b[8] = {b0.x, b0.y, b0.z, b0.w, b1.x, b1.y, b1.z, b1.w};
            #pragma unroll
            for (int i = 0; i < 8; i++)
                #pragma unroll
                for (int j = 0; j < 8; j++) acc[i][j] += a[i] * b[j];
        }
        __syncthreads();
    }

    // Epilogue: vectorized stores, add bias.
    float4 bb0 = *(const float4*)&bias[col0 + tx * 4];
    float4 bb1 = *(const float4*)&bias[col0 + tx * 4 + 64];
    #pragma unroll
    for (int i = 0; i < 8; i++) {
        int r = row0 + ((i < 4) ? (ty * 4 + i) : (64 + ty * 4 + i - 4));
        float4 o0 = make_float4(acc[i][0] + bb0.x, acc[i][1] + bb0.y,
                                acc[i][2] + bb0.z, acc[i][3] + bb0.w);
        float4 o1 = make_float4(acc[i][4] + bb1.x, acc[i][5] + bb1.y,
                                acc[i][6] + bb1.z, acc[i][7] + bb1.w);
        *(float4*)&C[(size_t)r * N + col0 + tx * 4]      = o0;
        *(float4*)&C[(size_t)r * N + col0 + tx * 4 + 64] = o1;
    }
}

// ---------------------------------------------------------------------------
// Fused masked-softmax attention (flash-style, fp32 SIMT).
//   s[q,k]   = scale * M[q,k] * (Q[q]·K[k])
//   A_bar    = M*exp(s-m) / (Zm + EPS*Z),  Z = sum exp(s-m), Zm = sum M*exp(s-m)
//   out[q]   = sum_k A_bar[q,k] * V[k]
// CTA: one (b, h, 64-query tile); 32 key blocks of 64. 256 threads.
// Thread owns 4q x 4k score microtile and 4q x 4d output microtile (same 4 q).
// ---------------------------------------------------------------------------
__global__ __launch_bounds__(256) void attn_kernel(
    const float* __restrict__ Qg, const float* __restrict__ Kg,
    const float* __restrict__ Vg, const float* __restrict__ Mg,
    float* __restrict__ Og)
{
    __shared__ __align__(16) float Qs[64][64];   // Q^T: [d][q]
    __shared__ __align__(16) float KPs[64][64];  // phase1: K^T [d][k]; phase2: P^T [k][q]
    __shared__ __align__(16) float Vs[64][64];   // V: [k][d]

    const int tid = threadIdx.x;
    const int qt  = tid >> 4;   // 0..15 : q group (shared between both phases)
    const int kt  = tid & 15;   // 0..15 : k group (phase1) / d group (phase2)
    const int b = blockIdx.z, h = blockIdx.y, qb = blockIdx.x;
    const float scale = 0.125f;                   // HD^-0.5
    const float LOG2E = 1.4426950408889634f;

    const float* Qbase = Qg + ((size_t)(b * S_ + qb * 64)) * D_ + h * HD_;
    const float* Kbase = Kg + ((size_t)b * S_) * D_ + h * HD_;
    const float* Vbase = Vg + ((size_t)b * S_) * D_ + h * HD_;
    const float* Mbase = Mg + (size_t)b * S_ * S_ + (size_t)(qb * 64) * S_;
    float*       Obase = Og + ((size_t)(b * S_ + qb * 64)) * D_ + h * HD_;

    // Load Q tile transposed.
    #pragma unroll
    for (int it = 0; it < 4; it++) {
        int idx = tid + 256 * it;
        int r = idx >> 4, c = (idx & 15) * 4;
        float4 v = *(const float4*)&Qbase[(size_t)r * D_ + c];
        Qs[c + 0][r] = v.x; Qs[c + 1][r] = v.y;
        Qs[c + 2][r] = v.z; Qs[c + 3][r] = v.w;
    }

    float m_run[4], Zs[4], Zm[4], acc[4][4];
    #pragma unroll
    for (int i = 0; i < 4; i++) {
        m_run[i] = -1e30f; Zs[i] = 0.0f; Zm[i] = 0.0f;
        #pragma unroll
        for (int j = 0; j < 4; j++) acc[i][j] = 0.0f;
    }
    __syncthreads();

    for (int kb = 0; kb < S_ / 64; kb++) {
        const float* Kb = Kbase + (size_t)(kb * 64) * D_;
        const float* Vb = Vbase + (size_t)(kb * 64) * D_;
        #pragma unroll
        for (int it = 0; it < 4; it++) {
            int idx = tid + 256 * it;
            int r = idx >> 4, c = (idx & 15) * 4;
            float4 kv = *(const float4*)&Kb[(size_t)r * D_ + c];
            KPs[c + 0][r] = kv.x; KPs[c + 1][r] = kv.y;
            KPs[c + 2][r] = kv.z; KPs[c + 3][r] = kv.w;
            *(float4*)&Vs[r][c] = *(const float4*)&Vb[(size_t)r * D_ + c];
        }
        __syncthreads();

        // --- scores: s = Q_tile @ K_tile^T ---
        float s[4][4];
        #pragma unroll
        for (int i = 0; i < 4; i++)
            #pragma unroll
            for (int j = 0; j < 4; j++) s[i][j] = 0.0f;

        #pragma unroll 16
        for (int d = 0; d < 64; d++) {
            float4 qv = *(const float4*)&Qs[d][qt * 4];
            float4 kv = *(const float4*)&KPs[d][kt * 4];
            float qa[4] = {qv.x, qv.y, qv.z, qv.w};
            float ka[4] = {kv.x, kv.y, kv.z, kv.w};
            #pragma unroll
            for (int i = 0; i < 4; i++)
                #pragma unroll
                for (int j = 0; j < 4; j++) s[i][j] += qa[i] * ka[j];
        }

        // --- mask * scale ---
        float mv[4][4];
        #pragma unroll
        for (int i = 0; i < 4; i++) {
            float4 m4 = *(const float4*)&Mbase[(size_t)(qt * 4 + i) * S_ + kb * 64 + kt * 4];
            mv[i][0] = m4.x; mv[i][1] = m4.y; mv[i][2] = m4.z; mv[i][3] = m4.w;
            #pragma unroll
            for (int j = 0; j < 4; j++) s[i][j] *= scale * mv[i][j];
        }

        // --- online softmax update (rows shared by 16 lanes) ---
        float corr[4];
        #pragma unroll
        for (int i = 0; i < 4; i++) {
            float rx = fmaxf(fmaxf(s[i][0], s[i][1]), fmaxf(s[i][2], s[i][3]));
            #pragma unroll
            for (int o = 8; o > 0; o >>= 1)
                rx = fmaxf(rx, __shfl_xor_sync(0xffffffffu, rx, o));
            float mn = fmaxf(m_run[i], rx);
            corr[i] = exp2f((m_run[i] - mn) * LOG2E);
            m_run[i] = mn;
        }
        #pragma unroll
        for (int i = 0; i < 4; i++) {
            float ls = 0.0f, lm = 0.0f;
            #pragma unroll
            for (int j = 0; j < 4; j++) {
                float p  = exp2f((s[i][j] - m_run[i]) * LOG2E);
                float pm = p * mv[i][j];
                s[i][j] = pm;            // reuse as numerator weights
                ls += p; lm += pm;
            }
            Zs[i] = Zs[i] * corr[i] + ls;
            Zm[i] = Zm[i] * corr[i] + lm;
        }

        __syncthreads();   // everyone done reading K^T before overwrite as P^T
        #pragma unroll
        for (int j = 0; j < 4; j++) {
            float4 pv = make_float4(s[0][j], s[1][j], s[2][j], s[3][j]);
            *(float4*)&KPs[kt * 4 + j][qt * 4] = pv;
        }
        __syncthreads();

        // --- out accumulation: acc = acc*corr + P^T-tile @ V-tile ---
        #pragma unroll
        for (int i = 0; i < 4; i++)
            #pragma unroll
            for (int j = 0; j < 4; j++) acc[i][j] *= corr[i];

        #pragma unroll 16
        for (int k = 0; k < 64; k++) {
            float4 pv = *(const float4*)&KPs[k][qt * 4];
            float4 vv = *(const float4*)&Vs[k][kt * 4];
            float pa[4] = {pv.x, pv.y, pv.z, pv.w};
            float va[4] = {vv.x, vv.y, vv.z, vv.w};
            #pragma unroll
            for (int i = 0; i < 4; i++)
                #pragma unroll
                for (int j = 0; j < 4; j++) acc[i][j] += pa[i] * va[j];
        }
        __syncthreads();
    }

    // Final reduce of Z, Zm across the 16 lanes sharing each q row.
    #pragma unroll
    for (int i = 0; i < 4; i++) {
        float zs = Zs[i], zm = Zm[i];
        #pragma unroll
        for (int o = 8; o > 0; o >>= 1) {
            zs += __shfl_xor_sync(0xffffffffu, zs, o);
            zm += __shfl_xor_sync(0xffffffffu, zm, o);
        }
        float inv = 1.0f / (zm + 1e-8f * zs);
        float4 o4 = make_float4(acc[i][0] * inv, acc[i][1] * inv,
                                acc[i][2] * inv, acc[i][3] * inv);
        *(float4*)&Obase[(size_t)(qt * 4 + i) * D_ + kt * 4] = o4;
    }
}

// ---------------------------------------------------------------------------
extern "C" void kernel_launch(void* const* d_in, const int* in_sizes, int n_in,
                              void* d_out, int out_size)
{
    const float* gene    = (const float*)d_in[0];
    const float* expr    = (const float*)d_in[1];
    const float* Mm      = (const float*)d_in[2];
    const float* W_fused = (const float*)d_in[3];
    const float* b_fused = (const float*)d_in[4];
    const float* W_Q     = (const float*)d_in[5];
    const float* b_Q     = (const float*)d_in[6];
    const float* W_K     = (const float*)d_in[7];
    const float* b_K     = (const float*)d_in[8];
    const float* W_V     = (const float*)d_in[9];
    const float* b_V     = (const float*)d_in[10];
    const float* W_O     = (const float*)d_in[11];
    const float* b_O     = (const float*)d_in[12];
    float* out = (float*)d_out;

    float *fusedp, *Qp, *Kp, *Vp, *attp;
    cudaGetSymbolAddress((void**)&fusedp, g_fused);
    cudaGetSymbolAddress((void**)&Qp, g_Q);
    cudaGetSymbolAddress((void**)&Kp, g_K);
    cudaGetSymbolAddress((void**)&Vp, g_V);
    cudaGetSymbolAddress((void**)&attp, g_att);

    dim3 gg(D_ / 128, NR / 128);   // (4, 64)

    // fused = [gene|expr] @ W_fused + b_fused
    sgemm_bias<<<gg, 256>>>(gene, expr, 512, W_fused, b_fused, fusedp, NR, D_, 1024);
    // Q, K from fused; V from expr
    sgemm_bias<<<gg, 256>>>(fusedp, fusedp, 512, W_Q, b_Q, Qp, NR, D_, 512);
    sgemm_bias<<<gg, 256>>>(fusedp, fusedp, 512, W_K, b_K, Kp, NR, D_, 512);
    sgemm_bias<<<gg, 256>>>(expr,   expr,   512, W_V, b_V, Vp, NR, D_, 512);
    // fused masked attention
    attn_kernel<<<dim3(S_ / 64, H_, B_), 256>>>(Qp, Kp, Vp, Mm, attp);
    // out = att @ W_O + b_O
    sgemm_bias<<<gg, 256>>>(attp, attp, 512, W_O, b_O, out, NR, D_, 512);
}

// round 3
// speedup vs baseline: 2.0182x; 2.0182x over previous
#include <cuda_runtime.h>
#include <math.h>
#include <stdint.h>

#define B_  4
#define S_  2048
#define D_  512
#define H_  8
#define HD_ 64
#define NR  (B_ * S_)   // 8192 rows

// Scratch buffers (no allocation allowed in kernel_launch).
__device__ __align__(16) float g_fused[NR * D_];
__device__ __align__(16) float g_Q[NR * D_];
__device__ __align__(16) float g_K[NR * D_];
__device__ __align__(16) float g_V[NR * D_];
__device__ __align__(16) float g_att[NR * D_];

// ---------------------------------------------------------------------------
// TF32 helpers
// ---------------------------------------------------------------------------
__device__ __forceinline__ uint32_t f2tf(float x) {
    uint32_t u;
    asm("cvt.rna.tf32.f32 %0, %1;" : "=r"(u) : "f"(x));
    return u;
}
__device__ __forceinline__ float f2tff(float x) {
    return __uint_as_float(f2tf(x));
}
// D(16x8,f32) += A(16x8,tf32,row) * B(8x8,tf32,col)
__device__ __forceinline__ void mma8(float* d, const uint32_t* a, const uint32_t* b) {
    asm volatile(
        "mma.sync.aligned.m16n8k8.row.col.f32.tf32.tf32.f32 "
        "{%0,%1,%2,%3}, {%4,%5,%6,%7}, {%8,%9}, {%0,%1,%2,%3};"
        : "+f"(d[0]), "+f"(d[1]), "+f"(d[2]), "+f"(d[3])
        : "r"(a[0]), "r"(a[1]), "r"(a[2]), "r"(a[3]), "r"(b[0]), "r"(b[1]));
}

// ---------------------------------------------------------------------------
// TF32 tensor-core GEMM: C[M,512] = A[M,K] @ Bw[K,512] + bias.
// Concat support: logical A row = A[0..KA) ++ A2[0..K-KA). 16-col k-tiles
// never straddle KA (512 | 16).
// CTA 128x128, 256 threads, 8 warps (2m x 4n), warp tile 64x32.
// ---------------------------------------------------------------------------
__global__ __launch_bounds__(256, 2) void gemm_tf32(
    const float* __restrict__ A, const float* __restrict__ A2, int KA,
    const float* __restrict__ Bw, const float* __restrict__ bias,
    float* __restrict__ C, int K)
{
    __shared__ float As[128][20];   // [m][k], pad 16->20: frag LDS conflict-free
    __shared__ float Bs[16][132];   // [k][n], pad 128->132

    const int tid  = threadIdx.x;
    const int lane = tid & 31, wid = tid >> 5;
    const int g = lane >> 2, t = lane & 3;
    const int wm = (wid >> 2) * 64;
    const int wn = (wid & 3) * 32;
    const int row0 = blockIdx.y * 128;
    const int col0 = blockIdx.x * 128;

    const int ar = tid >> 1;            // 0..127
    const int ac = (tid & 1) * 8;       // 0 or 8
    const int bk = tid >> 4;            // 0..15
    const int bc = (tid & 15) * 8;      // 0..120

    float acc[4][4][4];
    #pragma unroll
    for (int i = 0; i < 4; i++)
        #pragma unroll
        for (int j = 0; j < 4; j++)
            #pragma unroll
            for (int v = 0; v < 4; v++) acc[i][j][v] = 0.0f;

    const int niter = K >> 4;
    float4 pa0, pa1, pb0, pb1;

    // prologue load
    {
        const float* p = &A[(size_t)(row0 + ar) * KA + ac];
        pa0 = *(const float4*)p; pa1 = *(const float4*)(p + 4);
        const float* q = &Bw[(size_t)bk * D_ + col0 + bc];
        pb0 = *(const float4*)q; pb1 = *(const float4*)(q + 4);
    }

    for (int it = 0; it < niter; it++) {
        // store prefetched tile (convert to tf32)
        *(float4*)&As[ar][ac] = make_float4(f2tff(pa0.x), f2tff(pa0.y), f2tff(pa0.z), f2tff(pa0.w));
        *(float4*)&As[ar][ac + 4] = make_float4(f2tff(pa1.x), f2tff(pa1.y), f2tff(pa1.z), f2tff(pa1.w));
        *(float4*)&Bs[bk][bc] = make_float4(f2tff(pb0.x), f2tff(pb0.y), f2tff(pb0.z), f2tff(pb0.w));
        *(float4*)&Bs[bk][bc + 4] = make_float4(f2tff(pb1.x), f2tff(pb1.y), f2tff(pb1.z), f2tff(pb1.w));
        __syncthreads();

        if (it + 1 < niter) {
            int k0 = (it + 1) << 4;
            const float* src = (k0 < KA) ? A : A2;
            int koff = (k0 < KA) ? k0 : k0 - KA;
            const float* p = &src[(size_t)(row0 + ar) * KA + koff + ac];
            pa0 = *(const float4*)p; pa1 = *(const float4*)(p + 4);
            const float* q = &Bw[(size_t)(k0 + bk) * D_ + col0 + bc];
            pb0 = *(const float4*)q; pb1 = *(const float4*)(q + 4);
        }

        const uint32_t* Au = (const uint32_t*)As;
        const uint32_t* Bu = (const uint32_t*)Bs;
        #pragma unroll
        for (int ks = 0; ks < 2; ks++) {
            const int kk = ks * 8;
            uint32_t a[4][4];
            #pragma unroll
            for (int mt = 0; mt < 4; mt++) {
                int m = wm + mt * 16;
                a[mt][0] = Au[(m + g) * 20 + kk + t];
                a[mt][1] = Au[(m + g + 8) * 20 + kk + t];
                a[mt][2] = Au[(m + g) * 20 + kk + t + 4];
                a[mt][3] = Au[(m + g + 8) * 20 + kk + t + 4];
            }
            #pragma unroll
            for (int nt = 0; nt < 4; nt++) {
                int n = wn + nt * 8 + g;
                uint32_t bf[2] = { Bu[(kk + t) * 132 + n], Bu[(kk + t + 4) * 132 + n] };
                #pragma unroll
                for (int mt = 0; mt < 4; mt++) mma8(acc[mt][nt], a[mt], bf);
            }
        }
        __syncthreads();
    }

    // epilogue: bias + store (c0,c1 are adjacent cols -> float2)
    #pragma unroll
    for (int mt = 0; mt < 4; mt++) {
        int r = row0 + wm + mt * 16 + g;
        #pragma unroll
        for (int nt = 0; nt < 4; nt++) {
            int c = col0 + wn + nt * 8 + 2 * t;
            float b0v = bias[c], b1v = bias[c + 1];
            *(float2*)&C[(size_t)r * D_ + c] =
                make_float2(acc[mt][nt][0] + b0v, acc[mt][nt][1] + b1v);
            *(float2*)&C[(size_t)(r + 8) * D_ + c] =
                make_float2(acc[mt][nt][2] + b0v, acc[mt][nt][3] + b1v);
        }
    }
}

// ---------------------------------------------------------------------------
// TF32 fused masked-softmax attention (flash-style).
//   sL[q,k] = (scale*log2e) * M[q,k] * (Q[q]·K[k])
//   p = exp2(sL - mL);  Zs = sum p;  pm = p*M;  Zm = sum pm
//   out[q] = (sum_k pm * V[k]) / (Zm + EPS*Zs)
// CTA: 64 q rows, 128 threads (4 warps x 16q). 32 key blocks of 64.
// ---------------------------------------------------------------------------
#define AT_STRIDE 68
#define AT_TILE   (64 * AT_STRIDE)
#define ATTN_SMEM ((4 * AT_TILE + 4 * 16 * AT_STRIDE) * 4)   // 87040 B

__global__ __launch_bounds__(128) void attn_tf32(
    const float* __restrict__ Qg, const float* __restrict__ Kg,
    const float* __restrict__ Vg, const float* __restrict__ Mg,
    float* __restrict__ Og)
{
    extern __shared__ float sm[];
    float* Qs = sm;                      // [64][68] (q x d), tf32
    float* Ks = sm + AT_TILE;            // [64][68] (k x d), tf32
    float* Vs = sm + 2 * AT_TILE;        // [64][68] (k x d), tf32
    float* Ms = sm + 3 * AT_TILE;        // [64][68] (q x k), fp32
    float* Ps = sm + 4 * AT_TILE;        // [4][16][68] warp-private P, tf32

    const int tid  = threadIdx.x;
    const int lane = tid & 31, w = tid >> 5;
    const int g = lane >> 2, t = lane & 3;
    const int qw = w * 16;
    const int b = blockIdx.z, h = blockIdx.y, qb = blockIdx.x;

    const float CL = 0.125f * 1.4426950408889634f;   // scale * log2e

    const float* Qbase = Qg + ((size_t)(b * S_ + qb * 64)) * D_ + h * HD_;
    const float* Kbase = Kg + ((size_t)(b * S_)) * D_ + h * HD_;
    const float* Vbase = Vg + ((size_t)(b * S_)) * D_ + h * HD_;
    const float* Mbase = Mg + (size_t)b * S_ * S_ + (size_t)(qb * 64) * S_;
    float*       Obase = Og + ((size_t)(b * S_ + qb * 64)) * D_ + h * HD_;

    // Q tile -> smem (tf32)
    #pragma unroll
    for (int itl = 0; itl < 8; itl++) {
        int idx = itl * 128 + tid;                 // 0..1023
        int r = idx >> 4, c = (idx & 15) * 4;
        float4 v = *(const float4*)&Qbase[(size_t)r * D_ + c];
        *(float4*)&Qs[r * AT_STRIDE + c] =
            make_float4(f2tff(v.x), f2tff(v.y), f2tff(v.z), f2tff(v.w));
    }

    float acc[8][4];
    #pragma unroll
    for (int i = 0; i < 8; i++)
        #pragma unroll
        for (int v = 0; v < 4; v++) acc[i][v] = 0.0f;
    float mL0 = -1e30f, mL1 = -1e30f;
    float Zs0 = 0.f, Zs1 = 0.f, Zm0 = 0.f, Zm1 = 0.f;
    __syncthreads();

    for (int kb = 0; kb < S_ / 64; kb++) {
        // K, V, M tiles -> smem
        #pragma unroll
        for (int itl = 0; itl < 8; itl++) {
            int idx = itl * 128 + tid;
            int r = idx >> 4, c = (idx & 15) * 4;
            float4 kv = *(const float4*)&Kbase[(size_t)(kb * 64 + r) * D_ + c];
            float4 vv = *(const float4*)&Vbase[(size_t)(kb * 64 + r) * D_ + c];
            float4 mv = *(const float4*)&Mbase[(size_t)r * S_ + kb * 64 + c];
            *(float4*)&Ks[r * AT_STRIDE + c] =
                make_float4(f2tff(kv.x), f2tff(kv.y), f2tff(kv.z), f2tff(kv.w));
            *(float4*)&Vs[r * AT_STRIDE + c] =
                make_float4(f2tff(vv.x), f2tff(vv.y), f2tff(vv.z), f2tff(vv.w));
            *(float4*)&Ms[r * AT_STRIDE + c] = mv;
        }
        __syncthreads();

        // --- scores: S[16q,64k] = Q @ K^T (warp) ---
        const uint32_t* Qu = (const uint32_t*)Qs;
        const uint32_t* Ku = (const uint32_t*)Ks;
        float sc[8][4];
        #pragma unroll
        for (int nt = 0; nt < 8; nt++)
            #pragma unroll
            for (int v = 0; v < 4; v++) sc[nt][v] = 0.0f;

        #pragma unroll
        for (int ks = 0; ks < 8; ks++) {
            uint32_t a[4];
            a[0] = Qu[(qw + g) * AT_STRIDE + ks * 8 + t];
            a[1] = Qu[(qw + g + 8) * AT_STRIDE + ks * 8 + t];
            a[2] = Qu[(qw + g) * AT_STRIDE + ks * 8 + t + 4];
            a[3] = Qu[(qw + g + 8) * AT_STRIDE + ks * 8 + t + 4];
            #pragma unroll
            for (int nt = 0; nt < 8; nt++) {
                uint32_t bf[2] = { Ku[(nt * 8 + g) * AT_STRIDE + ks * 8 + t],
                                   Ku[(nt * 8 + g) * AT_STRIDE + ks * 8 + t + 4] };
                mma8(sc[nt], a, bf);
            }
        }

        // --- mask * scale (log2 domain), row max ---
        float mx0 = -1e30f, mx1 = -1e30f;
        #pragma unroll
        for (int nt = 0; nt < 8; nt++) {
            float2 mA = *(const float2*)&Ms[(qw + g) * AT_STRIDE + nt * 8 + 2 * t];
            float2 mB = *(const float2*)&Ms[(qw + g + 8) * AT_STRIDE + nt * 8 + 2 * t];
            sc[nt][0] *= CL * mA.x;
            sc[nt][1] *= CL * mA.y;
            sc[nt][2] *= CL * mB.x;
            sc[nt][3] *= CL * mB.y;
            mx0 = fmaxf(mx0, fmaxf(sc[nt][0], sc[nt][1]));
            mx1 = fmaxf(mx1, fmaxf(sc[nt][2], sc[nt][3]));
        }
        mx0 = fmaxf(mx0, __shfl_xor_sync(0xffffffffu, mx0, 1));
        mx0 = fmaxf(mx0, __shfl_xor_sync(0xffffffffu, mx0, 2));
        mx1 = fmaxf(mx1, __shfl_xor_sync(0xffffffffu, mx1, 1));
        mx1 = fmaxf(mx1, __shfl_xor_sync(0xffffffffu, mx1, 2));

        float nm0 = fmaxf(mL0, mx0), nm1 = fmaxf(mL1, mx1);
        float corr0 = exp2f(mL0 - nm0), corr1 = exp2f(mL1 - nm1);
        mL0 = nm0; mL1 = nm1;

        // --- exp, Z accumulation, P (= p*M) to warp-private smem as tf32 ---
        float ls0 = 0.f, ls1 = 0.f, lm0 = 0.f, lm1 = 0.f;
        float* Pw = Ps + w * 16 * AT_STRIDE;
        #pragma unroll
        for (int nt = 0; nt < 8; nt++) {
            float2 mA = *(const float2*)&Ms[(qw + g) * AT_STRIDE + nt * 8 + 2 * t];
            float2 mB = *(const float2*)&Ms[(qw + g + 8) * AT_STRIDE + nt * 8 + 2 * t];
            float p0 = exp2f(sc[nt][0] - mL0);
            float p1 = exp2f(sc[nt][1] - mL0);
            float p2 = exp2f(sc[nt][2] - mL1);
            float p3 = exp2f(sc[nt][3] - mL1);
            ls0 += p0 + p1; ls1 += p2 + p3;
            p0 *= mA.x; p1 *= mA.y; p2 *= mB.x; p3 *= mB.y;
            lm0 += p0 + p1; lm1 += p2 + p3;
            *(float2*)&Pw[g * AT_STRIDE + nt * 8 + 2 * t] =
                make_float2(f2tff(p0), f2tff(p1));
            *(float2*)&Pw[(g + 8) * AT_STRIDE + nt * 8 + 2 * t] =
                make_float2(f2tff(p2), f2tff(p3));
        }
        Zs0 = Zs0 * corr0 + ls0;  Zs1 = Zs1 * corr1 + ls1;
        Zm0 = Zm0 * corr0 + lm0;  Zm1 = Zm1 * corr1 + lm1;
        __syncwarp();   // order P stores before P fragment loads (same warp)

        // --- rescale out accumulators ---
        #pragma unroll
        for (int dt = 0; dt < 8; dt++) {
            acc[dt][0] *= corr0; acc[dt][1] *= corr0;
            acc[dt][2] *= corr1; acc[dt][3] *= corr1;
        }

        // --- out += P[16q,64k] @ V[64k,64d] ---
        const uint32_t* Pu = (const uint32_t*)Pw;
        const uint32_t* Vu = (const uint32_t*)Vs;
        #pragma unroll
        for (int ks = 0; ks < 8; ks++) {
            uint32_t a[4];
            a[0] = Pu[g * AT_STRIDE + ks * 8 + t];
            a[1] = Pu[(g + 8) * AT_STRIDE + ks * 8 + t];
            a[2] = Pu[g * AT_STRIDE + ks * 8 + t + 4];
            a[3] = Pu[(g + 8) * AT_STRIDE + ks * 8 + t + 4];
            #pragma unroll
            for (int dt = 0; dt < 8; dt++) {
                uint32_t bf[2] = { Vu[(ks * 8 + t) * AT_STRIDE + dt * 8 + g],
                                   Vu[(ks * 8 + t + 4) * AT_STRIDE + dt * 8 + g] };
                mma8(acc[dt], a, bf);
            }
        }
        __syncthreads();
    }

    // final: reduce Z over quad lanes, normalize, store
    Zs0 += __shfl_xor_sync(0xffffffffu, Zs0, 1);
    Zs0 += __shfl_xor_sync(0xffffffffu, Zs0, 2);
    Zs1 += __shfl_xor_sync(0xffffffffu, Zs1, 1);
    Zs1 += __shfl_xor_sync(0xffffffffu, Zs1, 2);
    Zm0 += __shfl_xor_sync(0xffffffffu, Zm0, 1);
    Zm0 += __shfl_xor_sync(0xffffffffu, Zm0, 2);
    Zm1 += __shfl_xor_sync(0xffffffffu, Zm1, 1);
    Zm1 += __shfl_xor_sync(0xffffffffu, Zm1, 2);
    float inv0 = 1.0f / (Zm0 + 1e-8f * Zs0);
    float inv1 = 1.0f / (Zm1 + 1e-8f * Zs1);

    #pragma unroll
    for (int dt = 0; dt < 8; dt++) {
        int c = dt * 8 + 2 * t;
        *(float2*)&Obase[(size_t)(qw + g) * D_ + c] =
            make_float2(acc[dt][0] * inv0, acc[dt][1] * inv0);
        *(float2*)&Obase[(size_t)(qw + g + 8) * D_ + c] =
            make_float2(acc[dt][2] * inv1, acc[dt][3] * inv1);
    }
}

// ---------------------------------------------------------------------------
extern "C" void kernel_launch(void* const* d_in, const int* in_sizes, int n_in,
                              void* d_out, int out_size)
{
    const float* gene    = (const float*)d_in[0];
    const float* expr    = (const float*)d_in[1];
    const float* Mm      = (const float*)d_in[2];
    const float* W_fused = (const float*)d_in[3];
    const float* b_fused = (const float*)d_in[4];
    const float* W_Q     = (const float*)d_in[5];
    const float* b_Q     = (const float*)d_in[6];
    const float* W_K     = (const float*)d_in[7];
    const float* b_K     = (const float*)d_in[8];
    const float* W_V     = (const float*)d_in[9];
    const float* b_V     = (const float*)d_in[10];
    const float* W_O     = (const float*)d_in[11];
    const float* b_O     = (const float*)d_in[12];
    float* out = (float*)d_out;

    float *fusedp, *Qp, *Kp, *Vp, *attp;
    cudaGetSymbolAddress((void**)&fusedp, g_fused);
    cudaGetSymbolAddress((void**)&Qp, g_Q);
    cudaGetSymbolAddress((void**)&Kp, g_K);
    cudaGetSymbolAddress((void**)&Vp, g_V);
    cudaGetSymbolAddress((void**)&attp, g_att);

    cudaFuncSetAttribute(attn_tf32,
                         cudaFuncAttributeMaxDynamicSharedMemorySize, ATTN_SMEM);

    dim3 gg(D_ / 128, NR / 128);   // (4, 64)

    gemm_tf32<<<gg, 256>>>(gene, expr, 512, W_fused, b_fused, fusedp, 1024);
    gemm_tf32<<<gg, 256>>>(fusedp, fusedp, 512, W_Q, b_Q, Qp, 512);
    gemm_tf32<<<gg, 256>>>(fusedp, fusedp, 512, W_K, b_K, Kp, 512);
    gemm_tf32<<<gg, 256>>>(expr,   expr,   512, W_V, b_V, Vp, 512);
    attn_tf32<<<dim3(S_ / 64, H_, B_), 128, ATTN_SMEM>>>(Qp, Kp, Vp, Mm, attp);
    gemm_tf32<<<gg, 256>>>(attp, attp, 512, W_O, b_O, out, 512);
}

// round 6
// speedup vs baseline: 2.3203x; 1.1497x over previous
#include <cuda_runtime.h>
#include <math.h>
#include <stdint.h>

#define B_  4
#define S_  2048
#define D_  512
#define H_  8
#define HD_ 64
#define NR  (B_ * S_)   // 8192 rows

// Scratch buffers (no allocation allowed in kernel_launch).
__device__ __align__(16) float g_fused[NR * D_];
__device__ __align__(16) float g_Q[NR * D_];
__device__ __align__(16) float g_K[NR * D_];
__device__ __align__(16) float g_V[NR * D_];
__device__ __align__(16) float g_att[NR * D_];

// ---------------------------------------------------------------------------
// TF32 helpers
// ---------------------------------------------------------------------------
__device__ __forceinline__ uint32_t f2tf(float x) {
    uint32_t u;
    asm("cvt.rna.tf32.f32 %0, %1;" : "=r"(u) : "f"(x));
    return u;
}
__device__ __forceinline__ float f2tff(float x) {
    return __uint_as_float(f2tf(x));
}
// D(16x8,f32) += A(16x8,tf32,row) * B(8x8,tf32,col)
__device__ __forceinline__ void mma8(float* d, const uint32_t* a, const uint32_t* b) {
    asm volatile(
        "mma.sync.aligned.m16n8k8.row.col.f32.tf32.tf32.f32 "
        "{%0,%1,%2,%3}, {%4,%5,%6,%7}, {%8,%9}, {%0,%1,%2,%3};"
        : "+f"(d[0]), "+f"(d[1]), "+f"(d[2]), "+f"(d[3])
        : "r"(a[0]), "r"(a[1]), "r"(a[2]), "r"(a[3]), "r"(b[0]), "r"(b[1]));
}

// ---------------------------------------------------------------------------
// TF32 tensor-core GEMM: C[M,512] = A[M,K] @ Bw[K,512] + bias.
// Double-buffered smem: one __syncthreads per k-iter, LDG prefetch overlaps mma.
// Concat support: logical A row = A[0..KA) ++ A2[0..K-KA). 16-col k-tiles
// never straddle KA (512 | 16).
// CTA 128x128, 256 threads, 8 warps (2m x 4n), warp tile 64x32.
// ---------------------------------------------------------------------------
__global__ __launch_bounds__(256, 2) void gemm_tf32(
    const float* __restrict__ A, const float* __restrict__ A2, int KA,
    const float* __restrict__ Bw, const float* __restrict__ bias,
    float* __restrict__ C, int K)
{
    __shared__ float As[2][128][20];   // [m][k], pad: frag LDS conflict-free
    __shared__ float Bs[2][16][132];   // [k][n]

    const int tid  = threadIdx.x;
    const int lane = tid & 31, wid = tid >> 5;
    const int g = lane >> 2, t = lane & 3;
    const int wm = (wid >> 2) * 64;
    const int wn = (wid & 3) * 32;
    const int row0 = blockIdx.y * 128;
    const int col0 = blockIdx.x * 128;

    const int ar = tid >> 1;            // 0..127
    const int ac = (tid & 1) * 8;       // 0 or 8
    const int bk = tid >> 4;            // 0..15
    const int bc = (tid & 15) * 8;      // 0..120

    float acc[4][4][4];
    #pragma unroll
    for (int i = 0; i < 4; i++)
        #pragma unroll
        for (int j = 0; j < 4; j++)
            #pragma unroll
            for (int v = 0; v < 4; v++) acc[i][j][v] = 0.0f;

    const int niter = K >> 4;
    float4 pa0, pa1, pb0, pb1;

    auto prefetch = [&](int it) {
        int k0 = it << 4;
        const float* src = (k0 < KA) ? A : A2;
        int koff = (k0 < KA) ? k0 : k0 - KA;
        const float* p = &src[(size_t)(row0 + ar) * KA + koff + ac];
        pa0 = *(const float4*)p; pa1 = *(const float4*)(p + 4);
        const float* q = &Bw[(size_t)(k0 + bk) * D_ + col0 + bc];
        pb0 = *(const float4*)q; pb1 = *(const float4*)(q + 4);
    };
    auto stage = [&](int buf) {
        *(float4*)&As[buf][ar][ac]     = make_float4(f2tff(pa0.x), f2tff(pa0.y), f2tff(pa0.z), f2tff(pa0.w));
        *(float4*)&As[buf][ar][ac + 4] = make_float4(f2tff(pa1.x), f2tff(pa1.y), f2tff(pa1.z), f2tff(pa1.w));
        *(float4*)&Bs[buf][bk][bc]     = make_float4(f2tff(pb0.x), f2tff(pb0.y), f2tff(pb0.z), f2tff(pb0.w));
        *(float4*)&Bs[buf][bk][bc + 4] = make_float4(f2tff(pb1.x), f2tff(pb1.y), f2tff(pb1.z), f2tff(pb1.w));
    };

    prefetch(0);
    stage(0);
    __syncthreads();

    for (int it = 0; it < niter; it++) {
        const int cur = it & 1;
        if (it + 1 < niter) prefetch(it + 1);

        const uint32_t* Au = (const uint32_t*)As[cur];
        const uint32_t* Bu = (const uint32_t*)Bs[cur];
        #pragma unroll
        for (int ks = 0; ks < 2; ks++) {
            const int kk = ks * 8;
            uint32_t a[4][4];
            #pragma unroll
            for (int mt = 0; mt < 4; mt++) {
                int m = wm + mt * 16;
                a[mt][0] = Au[(m + g) * 20 + kk + t];
                a[mt][1] = Au[(m + g + 8) * 20 + kk + t];
                a[mt][2] = Au[(m + g) * 20 + kk + t + 4];
                a[mt][3] = Au[(m + g + 8) * 20 + kk + t + 4];
            }
            #pragma unroll
            for (int nt = 0; nt < 4; nt++) {
                int n = wn + nt * 8 + g;
                uint32_t bf[2] = { Bu[(kk + t) * 132 + n], Bu[(kk + t + 4) * 132 + n] };
                #pragma unroll
                for (int mt = 0; mt < 4; mt++) mma8(acc[mt][nt], a[mt], bf);
            }
        }

        if (it + 1 < niter) {
            stage(cur ^ 1);
            __syncthreads();
        }
    }

    // epilogue: bias + store (c0,c1 adjacent cols -> float2)
    #pragma unroll
    for (int mt = 0; mt < 4; mt++) {
        int r = row0 + wm + mt * 16 + g;
        #pragma unroll
        for (int nt = 0; nt < 4; nt++) {
            int c = col0 + wn + nt * 8 + 2 * t;
            float b0v = bias[c], b1v = bias[c + 1];
            *(float2*)&C[(size_t)r * D_ + c] =
                make_float2(acc[mt][nt][0] + b0v, acc[mt][nt][1] + b1v);
            *(float2*)&C[(size_t)(r + 8) * D_ + c] =
                make_float2(acc[mt][nt][2] + b0v, acc[mt][nt][3] + b1v);
        }
    }
}

// ---------------------------------------------------------------------------
// TF32 fused masked-softmax attention (flash-style).
//   sL[q,k] = (scale*log2e) * M[q,k] * (Q[q]·K[k])
//   p = exp2(sL - mL);  Zs = sum p;  pm = p*M;  Zm = sum pm
//   out[q] = (sum_k pm * V[k]) / (Zm + EPS*Zs)
// CTA: 128 q rows, 256 threads (8 warps x 16q). 32 key blocks of 64.
// M is read directly from gmem (L2-resident) in the C-fragment pattern.
// ---------------------------------------------------------------------------
#define AT_STRIDE 68
#define ATTN_SMEM ((128 * AT_STRIDE + 2 * 64 * AT_STRIDE + 8 * 16 * AT_STRIDE) * 4)

__global__ __launch_bounds__(256) void attn_tf32(
    const float* __restrict__ Qg, const float* __restrict__ Kg,
    const float* __restrict__ Vg, const float* __restrict__ Mg,
    float* __restrict__ Og)
{
    extern __shared__ float sm[];
    float* Qs = sm;                            // [128][68] (q x d), tf32
    float* Ks = Qs + 128 * AT_STRIDE;          // [64][68]  (k x d), tf32
    float* Vs = Ks + 64 * AT_STRIDE;           // [64][68]  (k x d), tf32
    float* Ps = Vs + 64 * AT_STRIDE;           // [8][16][68] warp-private P, tf32

    const int tid  = threadIdx.x;
    const int lane = tid & 31, w = tid >> 5;
    const int g = lane >> 2, t = lane & 3;
    const int qw = w * 16;
    const int b = blockIdx.z, h = blockIdx.y, qb = blockIdx.x;

    const float CL = 0.125f * 1.4426950408889634f;   // scale * log2e

    const float* Qbase = Qg + ((size_t)(b * S_ + qb * 128)) * D_ + h * HD_;
    const float* Kbase = Kg + ((size_t)(b * S_)) * D_ + h * HD_;
    const float* Vbase = Vg + ((size_t)(b * S_)) * D_ + h * HD_;
    const float* Mrow0 = Mg + (size_t)b * S_ * S_ + (size_t)(qb * 128 + qw + g) * S_;
    const float* Mrow1 = Mrow0 + (size_t)8 * S_;
    float*       Obase = Og + ((size_t)(b * S_ + qb * 128)) * D_ + h * HD_;

    // Q tile -> smem (tf32): 128 rows x 64 cols
    #pragma unroll
    for (int itl = 0; itl < 8; itl++) {
        int idx = itl * 256 + tid;                 // 0..2047
        int r = idx >> 4, c = (idx & 15) * 4;
        float4 v = *(const float4*)&Qbase[(size_t)r * D_ + c];
        *(float4*)&Qs[r * AT_STRIDE + c] =
            make_float4(f2tff(v.x), f2tff(v.y), f2tff(v.z), f2tff(v.w));
    }

    float acc[8][4];
    #pragma unroll
    for (int i = 0; i < 8; i++)
        #pragma unroll
        for (int v = 0; v < 4; v++) acc[i][v] = 0.0f;
    float mL0 = -1e30f, mL1 = -1e30f;
    float Zs0 = 0.f, Zs1 = 0.f, Zm0 = 0.f, Zm1 = 0.f;
    __syncthreads();

    for (int kb = 0; kb < S_ / 64; kb++) {
        // K, V tiles -> smem: 64 rows x 64 cols each
        #pragma unroll
        for (int itl = 0; itl < 4; itl++) {
            int idx = itl * 256 + tid;             // 0..1023
            int r = idx >> 4, c = (idx & 15) * 4;
            float4 kv = *(const float4*)&Kbase[(size_t)(kb * 64 + r) * D_ + c];
            float4 vv = *(const float4*)&Vbase[(size_t)(kb * 64 + r) * D_ + c];
            *(float4*)&Ks[r * AT_STRIDE + c] =
                make_float4(f2tff(kv.x), f2tff(kv.y), f2tff(kv.z), f2tff(kv.w));
            *(float4*)&Vs[r * AT_STRIDE + c] =
                make_float4(f2tff(vv.x), f2tff(vv.y), f2tff(vv.z), f2tff(vv.w));
        }
        __syncthreads();

        // --- scores: S[16q,64k] = Q @ K^T (warp) ---
        const uint32_t* Qu = (const uint32_t*)Qs;
        const uint32_t* Ku = (const uint32_t*)Ks;
        float sc[8][4];
        #pragma unroll
        for (int nt = 0; nt < 8; nt++)
            #pragma unroll
            for (int v = 0; v < 4; v++) sc[nt][v] = 0.0f;

        #pragma unroll
        for (int ks = 0; ks < 8; ks++) {
            uint32_t a[4];
            a[0] = Qu[(qw + g) * AT_STRIDE + ks * 8 + t];
            a[1] = Qu[(qw + g + 8) * AT_STRIDE + ks * 8 + t];
            a[2] = Qu[(qw + g) * AT_STRIDE + ks * 8 + t + 4];
            a[3] = Qu[(qw + g + 8) * AT_STRIDE + ks * 8 + t + 4];
            #pragma unroll
            for (int nt = 0; nt < 8; nt++) {
                uint32_t bf[2] = { Ku[(nt * 8 + g) * AT_STRIDE + ks * 8 + t],
                                   Ku[(nt * 8 + g) * AT_STRIDE + ks * 8 + t + 4] };
                mma8(sc[nt], a, bf);
            }
        }

        // --- mask * scale (log2 domain) from gmem, row max ---
        const float* Mc0 = Mrow0 + kb * 64;
        const float* Mc1 = Mrow1 + kb * 64;
        float mx0 = -1e30f, mx1 = -1e30f;
        #pragma unroll
        for (int nt = 0; nt < 8; nt++) {
            float2 mA = *(const float2*)&Mc0[nt * 8 + 2 * t];
            float2 mB = *(const float2*)&Mc1[nt * 8 + 2 * t];
            sc[nt][0] *= CL * mA.x;
            sc[nt][1] *= CL * mA.y;
            sc[nt][2] *= CL * mB.x;
            sc[nt][3] *= CL * mB.y;
            mx0 = fmaxf(mx0, fmaxf(sc[nt][0], sc[nt][1]));
            mx1 = fmaxf(mx1, fmaxf(sc[nt][2], sc[nt][3]));
        }
        mx0 = fmaxf(mx0, __shfl_xor_sync(0xffffffffu, mx0, 1));
        mx0 = fmaxf(mx0, __shfl_xor_sync(0xffffffffu, mx0, 2));
        mx1 = fmaxf(mx1, __shfl_xor_sync(0xffffffffu, mx1, 1));
        mx1 = fmaxf(mx1, __shfl_xor_sync(0xffffffffu, mx1, 2));

        float nm0 = fmaxf(mL0, mx0), nm1 = fmaxf(mL1, mx1);
        float corr0 = exp2f(mL0 - nm0), corr1 = exp2f(mL1 - nm1);
        mL0 = nm0; mL1 = nm1;

        // --- exp, Z accumulation, P (= p*M) to warp-private smem as tf32 ---
        float ls0 = 0.f, ls1 = 0.f, lm0 = 0.f, lm1 = 0.f;
        float* Pw = Ps + w * 16 * AT_STRIDE;
        #pragma unroll
        for (int nt = 0; nt < 8; nt++) {
            float2 mA = *(const float2*)&Mc0[nt * 8 + 2 * t];   // L1 hit
            float2 mB = *(const float2*)&Mc1[nt * 8 + 2 * t];
            float p0 = exp2f(sc[nt][0] - mL0);
            float p1 = exp2f(sc[nt][1] - mL0);
            float p2 = exp2f(sc[nt][2] - mL1);
            float p3 = exp2f(sc[nt][3] - mL1);
            ls0 += p0 + p1; ls1 += p2 + p3;
            p0 *= mA.x; p1 *= mA.y; p2 *= mB.x; p3 *= mB.y;
            lm0 += p0 + p1; lm1 += p2 + p3;
            *(float2*)&Pw[g * AT_STRIDE + nt * 8 + 2 * t] =
                make_float2(f2tff(p0), f2tff(p1));
            *(float2*)&Pw[(g + 8) * AT_STRIDE + nt * 8 + 2 * t] =
                make_float2(f2tff(p2), f2tff(p3));
        }
        Zs0 = Zs0 * corr0 + ls0;  Zs1 = Zs1 * corr1 + ls1;
        Zm0 = Zm0 * corr0 + lm0;  Zm1 = Zm1 * corr1 + lm1;
        __syncwarp();   // order P stores before P fragment loads (same warp)

        // --- rescale out accumulators ---
        #pragma unroll
        for (int dt = 0; dt < 8; dt++) {
            acc[dt][0] *= corr0; acc[dt][1] *= corr0;
            acc[dt][2] *= corr1; acc[dt][3] *= corr1;
        }

        // --- out += P[16q,64k] @ V[64k,64d] ---
        const uint32_t* Pu = (const uint32_t*)Pw;
        const uint32_t* Vu = (const uint32_t*)Vs;
        #pragma unroll
        for (int ks = 0; ks < 8; ks++) {
            uint32_t a[4];
            a[0] = Pu[g * AT_STRIDE + ks * 8 + t];
            a[1] = Pu[(g + 8) * AT_STRIDE + ks * 8 + t];
            a[2] = Pu[g * AT_STRIDE + ks * 8 + t + 4];
            a[3] = Pu[(g + 8) * AT_STRIDE + ks * 8 + t + 4];
            #pragma unroll
            for (int dt = 0; dt < 8; dt++) {
                uint32_t bf[2] = { Vu[(ks * 8 + t) * AT_STRIDE + dt * 8 + g],
                                   Vu[(ks * 8 + t + 4) * AT_STRIDE + dt * 8 + g] };
                mma8(acc[dt], a, bf);
            }
        }
        __syncthreads();
    }

    // final: reduce Z over quad lanes, normalize, store
    Zs0 += __shfl_xor_sync(0xffffffffu, Zs0, 1);
    Zs0 += __shfl_xor_sync(0xffffffffu, Zs0, 2);
    Zs1 += __shfl_xor_sync(0xffffffffu, Zs1, 1);
    Zs1 += __shfl_xor_sync(0xffffffffu, Zs1, 2);
    Zm0 += __shfl_xor_sync(0xffffffffu, Zm0, 1);
    Zm0 += __shfl_xor_sync(0xffffffffu, Zm0, 2);
    Zm1 += __shfl_xor_sync(0xffffffffu, Zm1, 1);
    Zm1 += __shfl_xor_sync(0xffffffffu, Zm1, 2);
    float inv0 = 1.0f / (Zm0 + 1e-8f * Zs0);
    float inv1 = 1.0f / (Zm1 + 1e-8f * Zs1);

    #pragma unroll
    for (int dt = 0; dt < 8; dt++) {
        int c = dt * 8 + 2 * t;
        *(float2*)&Obase[(size_t)(qw + g) * D_ + c] =
            make_float2(acc[dt][0] * inv0, acc[dt][1] * inv0);
        *(float2*)&Obase[(size_t)(qw + g + 8) * D_ + c] =
            make_float2(acc[dt][2] * inv1, acc[dt][3] * inv1);
    }
}

// ---------------------------------------------------------------------------
extern "C" void kernel_launch(void* const* d_in, const int* in_sizes, int n_in,
                              void* d_out, int out_size)
{
    const float* gene    = (const float*)d_in[0];
    const float* expr    = (const float*)d_in[1];
    const float* Mm      = (const float*)d_in[2];
    const float* W_fused = (const float*)d_in[3];
    const float* b_fused = (const float*)d_in[4];
    const float* W_Q     = (const float*)d_in[5];
    const float* b_Q     = (const float*)d_in[6];
    const float* W_K     = (const float*)d_in[7];
    const float* b_K     = (const float*)d_in[8];
    const float* W_V     = (const float*)d_in[9];
    const float* b_V     = (const float*)d_in[10];
    const float* W_O     = (const float*)d_in[11];
    const float* b_O     = (const float*)d_in[12];
    float* out = (float*)d_out;

    float *fusedp, *Qp, *Kp, *Vp, *attp;
    cudaGetSymbolAddress((void**)&fusedp, g_fused);
    cudaGetSymbolAddress((void**)&Qp, g_Q);
    cudaGetSymbolAddress((void**)&Kp, g_K);
    cudaGetSymbolAddress((void**)&Vp, g_V);
    cudaGetSymbolAddress((void**)&attp, g_att);

    cudaFuncSetAttribute(attn_tf32,
                         cudaFuncAttributeMaxDynamicSharedMemorySize, ATTN_SMEM);

    dim3 gg(D_ / 128, NR / 128);   // (4, 64)

    gemm_tf32<<<gg, 256>>>(gene, expr, 512, W_fused, b_fused, fusedp, 1024);
    gemm_tf32<<<gg, 256>>>(fusedp, fusedp, 512, W_Q, b_Q, Qp, 512);
    gemm_tf32<<<gg, 256>>>(fusedp, fusedp, 512, W_K, b_K, Kp, 512);
    gemm_tf32<<<gg, 256>>>(expr,   expr,   512, W_V, b_V, Vp, 512);
    attn_tf32<<<dim3(S_ / 128, H_, B_), 256, ATTN_SMEM>>>(Qp, Kp, Vp, Mm, attp);
    gemm_tf32<<<gg, 256>>>(attp, attp, 512, W_O, b_O, out, 512);
}